// round 8
// baseline (speedup 1.0000x reference)
#include <cuda_runtime.h>
#include <cstdint>

#define IMG_H 1024
#define IMG_W 1024
#define NB 8
#define HW (IMG_H * IMG_W)

#define EPS_G 1e-3f          // gate margin   (fp32 gm err worst-case ~1e-4)
#define EPS_T 1e-3f          // threshold margin vs 2.5 / 5.0
#define EPS_O 1e-3f          // orientation margin (d * |grad|)
#define MAX_FLAGS (1 << 20)

// Scratch (static device globals; no runtime allocation).
__device__ float         g_gmt[(size_t)NB * HW]; // gm PLANE-major [b][pix] (coalesced writes)
__device__ unsigned char g_idx[(size_t)NB * HW]; // ip(3b) | unc(1b) | alt(3b)<<4
__device__ float         g_thin[(size_t)NB * HW];
__device__ int           g_flag_count;
__device__ unsigned int  g_flags[MAX_FLAGS];     // b<<20 | y<<10 | x

// neighbor offsets of dir filter k: 0:E 1:SE 2:S 3:SW 4:W 5:NW 6:N 7:NE
__constant__ int c_dy[8] = {0, 1, 1, 1, 0, -1, -1, -1};
__constant__ int c_dx[8] = {1, 1, 0, -1, -1, -1, 0, 1};

// ---------------------------------------------------------------------------
// Compensated (float-float) arithmetic; all _rn so fast-math can't perturb it.
// ---------------------------------------------------------------------------
__device__ __forceinline__ void two_sum(float a, float b, float& s, float& e) {
    s = __fadd_rn(a, b);
    float bv = __fsub_rn(s, a);
    e = __fadd_rn(__fsub_rn(a, __fsub_rn(s, bv)), __fsub_rn(b, bv));
}

struct DAcc { float hi, err; };
__device__ __forceinline__ void dacc_init(DAcc& A) { A.hi = 0.f; A.err = 0.f; }

__device__ __forceinline__ void dacc_fmaff(DAcc& A, float a, float b) {
    float p = __fmul_rn(a, b);
    float e = __fmaf_rn(a, b, -p);
    float s, e2; two_sum(A.hi, p, s, e2);
    A.hi = s;
    A.err = __fadd_rn(A.err, __fadd_rn(e, e2));
}

__device__ __forceinline__ void dacc_fmadf(DAcc& A, float2 v, float w) {
    float p = __fmul_rn(v.x, w);
    float e = __fmaf_rn(v.x, w, -p);
    e = __fmaf_rn(v.y, w, e);
    float s, e2; two_sum(A.hi, p, s, e2);
    A.hi = s;
    A.err = __fadd_rn(A.err, __fadd_rn(e, e2));
}

__device__ __forceinline__ void dacc_adddf(DAcc& A, float2 v) {
    float s, e2; two_sum(A.hi, v.x, s, e2);
    A.hi = s;
    A.err = __fadd_rn(A.err, __fadd_rn(v.y, e2));
}

__device__ __forceinline__ float2 dacc_renorm(const DAcc& A) {
    float hi = __fadd_rn(A.hi, A.err);
    float lo = __fsub_rn(A.err, __fsub_rn(hi, A.hi));
    return make_float2(hi, lo);
}

__device__ __forceinline__ float2 df_add(float2 a, float2 b) {
    float s, e; two_sum(a.x, b.x, s, e);
    e = __fadd_rn(e, __fadd_rn(a.y, b.y));
    float hi = __fadd_rn(s, e);
    float lo = __fsub_rn(e, __fsub_rn(hi, s));
    return make_float2(hi, lo);
}

__device__ __forceinline__ float2 df_sub(float2 a, float2 b) {
    return df_add(a, make_float2(-b.x, -b.y));
}

__device__ __forceinline__ float2 df_scale2(float2 a) {
    return make_float2(__fmul_rn(a.x, 2.f), __fmul_rn(a.y, 2.f));
}

__device__ __forceinline__ float2 df_sqr(float2 a) {
    float p = __fmul_rn(a.x, a.x);
    float e = __fmaf_rn(a.x, a.x, -p);
    e = __fmaf_rn(__fmul_rn(2.f, a.x), a.y, e);
    return make_float2(p, e);
}

__device__ __forceinline__ float2 df_sqrt(float2 a) {
    if (!(a.x > 1e-37f)) {
        float h = a.x > 0.f ? a.x : 0.f;
        return make_float2(__fsqrt_rn(h), 0.f);
    }
    float y = __fsqrt_rn(a.x);
    float p = __fmul_rn(y, y);
    float e = __fmaf_rn(y, y, -p);
    float d = __fsub_rn(a.x, p);
    float num = __fadd_rn(d, __fsub_rn(a.y, e));
    float c = __fdividef(num, __fmul_rn(2.f, y));
    float hi = __fadd_rn(y, c);
    float lo = __fsub_rn(c, __fsub_rn(hi, y));
    return make_float2(hi, lo);
}

// ---------------------------------------------------------------------------
// df64 single-pixel recompute (same operation order as the validated df64 A).
// DIR=false skips the gx/gy accumulators (gate-only calls).
// ---------------------------------------------------------------------------
template <bool DIR>
__device__ void gm_df(const float* __restrict__ img, const float* __restrict__ gv,
                      int q, int y, int x, float& fgm, float& fgx, float& fgy)
{
    DAcc MAG, GXS, GYS;
    dacc_init(MAG); dacc_init(GXS); dacc_init(GYS);

    for (int c = 0; c < 3; ++c) {
        const float* __restrict__ src = img + (size_t)(q * 3 + c) * HW;

        float raw[7][7];
        #pragma unroll
        for (int ry = 0; ry < 7; ++ry) {
            int yy = y - 3 + ry;
            bool rowok = (unsigned)yy < IMG_H;
            #pragma unroll
            for (int rx = 0; rx < 7; ++rx) {
                int xx = x - 3 + rx;
                raw[ry][rx] = (rowok && (unsigned)xx < IMG_W) ? src[yy * IMG_W + xx] : 0.f;
            }
        }

        float2 hb[7][3];
        #pragma unroll
        for (int ry = 0; ry < 7; ++ry) {
            #pragma unroll
            for (int rx = 0; rx < 3; ++rx) {
                DAcc A; dacc_init(A);
                dacc_fmaff(A, gv[0], raw[ry][rx]);
                dacc_fmaff(A, gv[1], raw[ry][rx + 1]);
                dacc_fmaff(A, gv[2], raw[ry][rx + 2]);
                dacc_fmaff(A, gv[3], raw[ry][rx + 3]);
                dacc_fmaff(A, gv[4], raw[ry][rx + 4]);
                hb[ry][rx] = dacc_renorm(A);
            }
        }

        float2 bl[3][3];
        #pragma unroll
        for (int by = 0; by < 3; ++by) {
            int yy = y - 1 + by;
            #pragma unroll
            for (int bx = 0; bx < 3; ++bx) {
                int xx = x - 1 + bx;
                float2 v = make_float2(0.f, 0.f);
                if ((unsigned)yy < IMG_H && (unsigned)xx < IMG_W) {
                    DAcc A; dacc_init(A);
                    dacc_fmadf(A, hb[by][bx],     gv[0]);
                    dacc_fmadf(A, hb[by + 1][bx], gv[1]);
                    dacc_fmadf(A, hb[by + 2][bx], gv[2]);
                    dacc_fmadf(A, hb[by + 3][bx], gv[3]);
                    dacc_fmadf(A, hb[by + 4][bx], gv[4]);
                    v = dacc_renorm(A);
                }
                bl[by][bx] = v;
            }
        }

        float2 gx = df_add(df_add(df_sub(bl[0][0], bl[0][2]), df_sub(bl[2][0], bl[2][2])),
                           df_scale2(df_sub(bl[1][0], bl[1][2])));
        float2 gy = df_add(df_add(df_sub(bl[0][0], bl[2][0]), df_sub(bl[0][2], bl[2][2])),
                           df_scale2(df_sub(bl[0][1], bl[2][1])));

        float2 m = df_sqrt(df_add(df_sqr(gx), df_sqr(gy)));
        dacc_adddf(MAG, m);
        if (DIR) { dacc_adddf(GXS, gx); dacc_adddf(GYS, gy); }
    }
    fgm = dacc_renorm(MAG).x;
    if (DIR) { fgx = dacc_renorm(GXS).x; fgy = dacc_renorm(GYS).x; }
}

// ---------------------------------------------------------------------------
// Kernel A (fp32 fast path). Structured (tx,ty) loops — no div/mod.
// gm written PLANE-major -> fully coalesced stores.
// ---------------------------------------------------------------------------
__global__ __launch_bounds__(256) void canny_grad_fp32(
    const float* __restrict__ img, const float* __restrict__ gw)
{
    if (blockIdx.x == 0 && blockIdx.y == 0 && blockIdx.z == 0 &&
        threadIdx.x == 0 && threadIdx.y == 0)
        g_flag_count = 0;

    const int b  = blockIdx.z;
    const int x0 = blockIdx.x * 32;
    const int y0 = blockIdx.y * 32;
    const int tx = threadIdx.x, ty = threadIdx.y;

    __shared__ float s_raw[38][40];
    __shared__ float s_hb[38][36];
    __shared__ float s_bl[34][36];

    const float g0 = gw[0], g1 = gw[1], g2 = gw[2], g3 = gw[3], g4 = gw[4];

    float mag[4] = {0.f, 0.f, 0.f, 0.f};
    float gxs[4] = {0.f, 0.f, 0.f, 0.f};
    float gys[4] = {0.f, 0.f, 0.f, 0.f};

    for (int c = 0; c < 3; ++c) {
        const float* __restrict__ src = img + (size_t)(b * 3 + c) * HW;

        // raw 38x38, zero padded
        for (int r = ty; r < 38; r += 8) {
            int gy = y0 - 3 + r;
            bool rowok = (unsigned)gy < IMG_H;
            {
                int gx = x0 - 3 + tx;
                s_raw[r][tx] = (rowok && (unsigned)gx < IMG_W) ? src[gy * IMG_W + gx] : 0.f;
            }
            if (tx < 6) {
                int gx = x0 - 3 + tx + 32;
                s_raw[r][tx + 32] = (rowok && (unsigned)gx < IMG_W) ? src[gy * IMG_W + gx] : 0.f;
            }
        }
        __syncthreads();

        // hblur 38x34 (col cc -> x = x0-1+cc)
        for (int r = ty; r < 38; r += 8) {
            s_hb[r][tx] = g0 * s_raw[r][tx] + g1 * s_raw[r][tx + 1] +
                          g2 * s_raw[r][tx + 2] + g3 * s_raw[r][tx + 3] +
                          g4 * s_raw[r][tx + 4];
            if (tx < 2) {
                int cc = tx + 32;
                s_hb[r][cc] = g0 * s_raw[r][cc] + g1 * s_raw[r][cc + 1] +
                              g2 * s_raw[r][cc + 2] + g3 * s_raw[r][cc + 3] +
                              g4 * s_raw[r][cc + 4];
            }
        }
        __syncthreads();

        // vblur 34x34; sobel sees zeros OOB -> force 0
        for (int r = ty; r < 34; r += 8) {
            int gy = y0 - 1 + r;
            bool rowok = (unsigned)gy < IMG_H;
            {
                int gx = x0 - 1 + tx;
                float v = 0.f;
                if (rowok && (unsigned)gx < IMG_W)
                    v = g0 * s_hb[r][tx] + g1 * s_hb[r + 1][tx] + g2 * s_hb[r + 2][tx] +
                        g3 * s_hb[r + 3][tx] + g4 * s_hb[r + 4][tx];
                s_bl[r][tx] = v;
            }
            if (tx < 2) {
                int cc = tx + 32;
                int gx = x0 - 1 + cc;
                float v = 0.f;
                if (rowok && (unsigned)gx < IMG_W)
                    v = g0 * s_hb[r][cc] + g1 * s_hb[r + 1][cc] + g2 * s_hb[r + 2][cc] +
                        g3 * s_hb[r + 3][cc] + g4 * s_hb[r + 4][cc];
                s_bl[r][cc] = v;
            }
        }
        __syncthreads();

        #pragma unroll
        for (int k = 0; k < 4; ++k) {
            int row = ty + k * 8;
            float b00 = s_bl[row][tx],     b01 = s_bl[row][tx + 1],     b02 = s_bl[row][tx + 2];
            float b10 = s_bl[row + 1][tx],                              b12 = s_bl[row + 1][tx + 2];
            float b20 = s_bl[row + 2][tx], b21 = s_bl[row + 2][tx + 1], b22 = s_bl[row + 2][tx + 2];
            float gx = (b00 - b02) + 2.f * (b10 - b12) + (b20 - b22);
            float gy = (b00 + 2.f * b01 + b02) - (b20 + 2.f * b21 + b22);
            mag[k] += sqrtf(gx * gx + gy * gy);
            gxs[k] += gx;
            gys[k] += gy;
        }
        __syncthreads();
    }

    #pragma unroll
    for (int k = 0; k < 4; ++k) {
        int row = ty + k * 8;
        int y = y0 + row, x = x0 + tx;
        int pix = y * IMG_W + x;

        float t = atan2f(gys[k], gxs[k]);
        float o = t * 57.29577951308232f + 180.0f;
        float u = o / 45.0f;
        float kf = rintf(u);
        int ip = ((int)kf) & 7;

        float fl = floorf(u);
        float d  = fabsf((u - fl) - 0.5f);
        float r  = sqrtf(gxs[k] * gxs[k] + gys[k] * gys[k]);
        bool unc = (d * r < EPS_O) || (d < 4e-5f);
        int iplo = ((int)fl) & 7;
        int iphi = ((int)fl + 1) & 7;
        int alt  = (ip == iplo) ? iphi : iplo;

        g_gmt[(size_t)b * HW + pix] = mag[k];           // plane-major: coalesced
        g_idx[(size_t)b * HW + pix] =
            (unsigned char)(ip | (unc ? 8 : 0) | (alt << 4));
    }
}

// ---------------------------------------------------------------------------
// Kernel B: NMS + threshold + hysteresis (fp32), thin store + uncertainty flags.
// Stages the 8 gm planes once per tile region (plane-major reads).
// ---------------------------------------------------------------------------
__global__ __launch_bounds__(256) void canny_nms_kernel(float* __restrict__ out)
{
    const int x0 = blockIdx.x * 32;
    const int y0 = blockIdx.y * 32;
    const int tx = threadIdx.x, ty = threadIdx.y;

    __shared__ float s_gm[NB][36][38];
    __shared__ float s_thin[34][36];

    #pragma unroll
    for (int p = 0; p < NB; ++p) {
        const float* __restrict__ plane = &g_gmt[(size_t)p * HW];
        for (int r = ty; r < 36; r += 8) {
            int y = y0 - 2 + r;
            bool rowok = (unsigned)y < IMG_H;
            {
                int x = x0 - 2 + tx;
                s_gm[p][r][tx] = (rowok && (unsigned)x < IMG_W) ? plane[y * IMG_W + x] : 0.f;
            }
            if (tx < 4) {
                int x = x0 - 2 + tx + 32;
                s_gm[p][r][tx + 32] = (rowok && (unsigned)x < IMG_W) ? plane[y * IMG_W + x] : 0.f;
            }
        }
    }
    __syncthreads();

    for (int b = 0; b < NB; ++b) {
        const int dy = c_dy[b], dx = c_dx[b];

        auto thin_body = [&](int r, int cc) {
            int y = y0 - 1 + r, x = x0 - 1 + cc;
            float thin = 0.f;
            if ((unsigned)y < IMG_H && (unsigned)x < IMG_W) {
                int pix = y * IMG_W + x;
                int byte = g_idx[(size_t)b * HW + pix];
                int ip  = byte & 7;
                int in_ = (ip + 4) & 7;
                int gr = r + 1, gc = cc + 1;
                float sp = s_gm[ip][gr][gc]  - s_gm[ip][gr + dy][gc + dx];
                float sn = s_gm[in_][gr][gc] - s_gm[in_][gr + dy][gc + dx];
                float mn = fminf(sp, sn);
                bool gate = mn > 0.f;
                float gmb = s_gm[b][gr][gc];
                if (gate) thin = gmb;

                if (r >= 1 && r <= 32 && cc >= 1 && cc <= 32) {   // core pixel
                    g_thin[(size_t)b * HW + pix] = thin;
                    if (gmb > 2.5f - EPS_T) {
                        bool unc = fabsf(mn) < EPS_G;
                        if (!unc && gate &&
                            (fabsf(gmb - 2.5f) < EPS_T || fabsf(gmb - 5.f) < EPS_T))
                            unc = true;
                        if (!unc && (byte & 8)) {
                            int ia  = (byte >> 4) & 7;
                            int ina = (ia + 4) & 7;
                            float sp2 = s_gm[ia][gr][gc]  - s_gm[ia][gr + dy][gc + dx];
                            float sn2 = s_gm[ina][gr][gc] - s_gm[ina][gr + dy][gc + dx];
                            float mn2 = fminf(sp2, sn2);
                            if ((mn2 > 0.f) != gate || fabsf(mn2) < EPS_G) unc = true;
                        }
                        if (unc) {
                            int s = atomicAdd(&g_flag_count, 1);
                            if (s < MAX_FLAGS)
                                g_flags[s] = ((unsigned)b << 20) | ((unsigned)y << 10) | (unsigned)x;
                        }
                    }
                }
            }
            s_thin[r][cc] = thin;
        };

        for (int r = ty; r < 34; r += 8) {
            thin_body(r, tx);
            if (tx < 2) thin_body(r, tx + 32);
        }
        __syncthreads();

        #pragma unroll
        for (int k = 0; k < 4; ++k) {
            int tyk = ty + k * 8;
            int y = y0 + tyk, x = x0 + tx;
            float t = s_thin[tyk + 1][tx + 1];
            float res;
            if (t > 5.0f) {
                res = 1.f;
            } else if (t >= 2.5f) {
                bool any =
                    s_thin[tyk][tx]     > 5.f || s_thin[tyk][tx + 1]     > 5.f || s_thin[tyk][tx + 2]     > 5.f ||
                    s_thin[tyk + 1][tx] > 5.f ||                                  s_thin[tyk + 1][tx + 2] > 5.f ||
                    s_thin[tyk + 2][tx] > 5.f || s_thin[tyk + 2][tx + 1] > 5.f || s_thin[tyk + 2][tx + 2] > 5.f;
                res = any ? 1.f : 0.f;
            } else {
                res = 0.f;
            }
            if (y == 0 || y == IMG_H - 1 || x == 0 || x == IMG_W - 1) res = 0.f;
            out[(size_t)b * HW + y * IMG_W + x] = res;
        }
        __syncthreads();
    }
}

// ---------------------------------------------------------------------------
// Kernel C: exact df64 recompute of flagged thin pixels (grid-stride).
// ---------------------------------------------------------------------------
__global__ __launch_bounds__(256) void canny_fix_kernel(
    const float* __restrict__ img, const float* __restrict__ gw)
{
    int n = g_flag_count;
    if (n > MAX_FLAGS) n = MAX_FLAGS;

    float gv[5];
    #pragma unroll
    for (int k = 0; k < 5; ++k) gv[k] = gw[k];

    for (int i = blockIdx.x * blockDim.x + threadIdx.x; i < n;
         i += gridDim.x * blockDim.x) {
        unsigned f = g_flags[i];
        int b = f >> 20, y = (f >> 10) & 1023, x = f & 1023;

        float fgm, fgx, fgy;
        gm_df<true>(img, gv, b, y, x, fgm, fgx, fgy);

        float t = atan2f(fgy, fgx);
        float o = __fadd_rn(__fmul_rn(t, 57.29577951308232f), 180.0f);
        float kf = rintf(__fdiv_rn(o, 45.0f));
        int ip  = ((int)kf) & 7;
        int in_ = (ip + 4) & 7;

        int dy = c_dy[b], dx = c_dx[b];
        int y2 = y + dy, x2 = x + dx;
        bool nb_ok = (unsigned)y2 < IMG_H && (unsigned)x2 < IMG_W;

        float dd1, dd2;
        float a0, a1, c0, c1;
        gm_df<false>(img, gv, ip, y, x, a0, dd1, dd2);
        if (nb_ok) gm_df<false>(img, gv, ip, y2, x2, a1, dd1, dd2); else a1 = 0.f;
        gm_df<false>(img, gv, in_, y, x, c0, dd1, dd2);
        if (nb_ok) gm_df<false>(img, gv, in_, y2, x2, c1, dd1, dd2); else c1 = 0.f;

        float sp = __fsub_rn(a0, a1);
        float sn = __fsub_rn(c0, c1);
        float thin = (fminf(sp, sn) > 0.f) ? fgm : 0.f;
        g_thin[(size_t)b * HW + y * IMG_W + x] = thin;
    }
}

// ---------------------------------------------------------------------------
// Kernel D: re-classify 3x3 outputs around each corrected thin (grid-stride).
// ---------------------------------------------------------------------------
__global__ __launch_bounds__(256) void canny_reclass_kernel(float* __restrict__ out)
{
    int n = g_flag_count;
    if (n > MAX_FLAGS) n = MAX_FLAGS;

    for (int i = blockIdx.x * blockDim.x + threadIdx.x; i < n;
         i += gridDim.x * blockDim.x) {
        unsigned f = g_flags[i];
        int b = f >> 20, y = (f >> 10) & 1023, x = f & 1023;
        const float* tb = &g_thin[(size_t)b * HW];

        #pragma unroll
        for (int dy2 = -1; dy2 <= 1; ++dy2) {
            #pragma unroll
            for (int dx2 = -1; dx2 <= 1; ++dx2) {
                int yo = y + dy2, xo = x + dx2;
                if ((unsigned)yo >= IMG_H || (unsigned)xo >= IMG_W) continue;
                float res = 0.f;
                if (yo > 0 && yo < IMG_H - 1 && xo > 0 && xo < IMG_W - 1) {
                    float t = tb[yo * IMG_W + xo];
                    if (t > 5.0f) {
                        res = 1.f;
                    } else if (t >= 2.5f) {
                        bool any =
                            tb[(yo - 1) * IMG_W + xo - 1] > 5.f || tb[(yo - 1) * IMG_W + xo] > 5.f || tb[(yo - 1) * IMG_W + xo + 1] > 5.f ||
                            tb[yo * IMG_W + xo - 1]       > 5.f ||                                    tb[yo * IMG_W + xo + 1]       > 5.f ||
                            tb[(yo + 1) * IMG_W + xo - 1] > 5.f || tb[(yo + 1) * IMG_W + xo] > 5.f || tb[(yo + 1) * IMG_W + xo + 1] > 5.f;
                        res = any ? 1.f : 0.f;
                    }
                }
                out[(size_t)b * HW + yo * IMG_W + xo] = res;
            }
        }
    }
}

// ---------------------------------------------------------------------------
extern "C" void kernel_launch(void* const* d_in, const int* in_sizes, int n_in,
                              void* d_out, int out_size)
{
    const float* img   = (const float*)d_in[0];  // (8,3,1024,1024)
    const float* gauss = (const float*)d_in[1];  // gauss_h (1,1,1,5)
    (void)in_sizes; (void)n_in; (void)out_size;

    dim3 blkA(32, 8);
    dim3 gridA(IMG_W / 32, IMG_H / 32, NB);
    canny_grad_fp32<<<gridA, blkA>>>(img, gauss);

    dim3 blkB(32, 8);
    dim3 gridB(IMG_W / 32, IMG_H / 32);
    canny_nms_kernel<<<gridB, blkB>>>((float*)d_out);

    canny_fix_kernel<<<512, 256>>>(img, gauss);
    canny_reclass_kernel<<<512, 256>>>((float*)d_out);
}

// round 9
// speedup vs baseline: 1.2232x; 1.2232x over previous
#include <cuda_runtime.h>
#include <cstdint>

#define IMG_H 1024
#define IMG_W 1024
#define NB 8
#define HW (IMG_H * IMG_W)

#define EPS_G 1e-3f          // gate margin   (fp32 gm err worst-case ~1e-4)
#define EPS_T 1e-3f          // threshold margin vs 2.5 / 5.0
#define EPS_O 1e-3f          // orientation margin (d * |grad|)
#define MAX_FLAGS (1 << 20)

// Scratch (static device globals; no runtime allocation).
__device__ float         g_gmt[HW * NB];          // gm pixel-major [pix][plane]
__device__ unsigned char g_idx[NB * HW];          // ip(3b) | unc(1b) | alt(3b)<<4
__device__ float         g_thin[(size_t)NB * HW]; // thin values (fp32, patched by C)
__device__ int           g_flag_count;
__device__ unsigned int  g_flags[MAX_FLAGS];      // b<<20 | y<<10 | x

// neighbor offsets of dir filter k: 0:E 1:SE 2:S 3:SW 4:W 5:NW 6:N 7:NE
__constant__ int c_dy[8] = {0, 1, 1, 1, 0, -1, -1, -1};
__constant__ int c_dx[8] = {1, 1, 0, -1, -1, -1, 0, 1};

// ---------------------------------------------------------------------------
// Compensated (float-float) arithmetic; all _rn so fast-math can't perturb it.
// ---------------------------------------------------------------------------
__device__ __forceinline__ void two_sum(float a, float b, float& s, float& e) {
    s = __fadd_rn(a, b);
    float bv = __fsub_rn(s, a);
    e = __fadd_rn(__fsub_rn(a, __fsub_rn(s, bv)), __fsub_rn(b, bv));
}

struct DAcc { float hi, err; };
__device__ __forceinline__ void dacc_init(DAcc& A) { A.hi = 0.f; A.err = 0.f; }

__device__ __forceinline__ void dacc_fmaff(DAcc& A, float a, float b) {
    float p = __fmul_rn(a, b);
    float e = __fmaf_rn(a, b, -p);
    float s, e2; two_sum(A.hi, p, s, e2);
    A.hi = s;
    A.err = __fadd_rn(A.err, __fadd_rn(e, e2));
}

__device__ __forceinline__ void dacc_fmadf(DAcc& A, float2 v, float w) {
    float p = __fmul_rn(v.x, w);
    float e = __fmaf_rn(v.x, w, -p);
    e = __fmaf_rn(v.y, w, e);
    float s, e2; two_sum(A.hi, p, s, e2);
    A.hi = s;
    A.err = __fadd_rn(A.err, __fadd_rn(e, e2));
}

__device__ __forceinline__ void dacc_adddf(DAcc& A, float2 v) {
    float s, e2; two_sum(A.hi, v.x, s, e2);
    A.hi = s;
    A.err = __fadd_rn(A.err, __fadd_rn(v.y, e2));
}

__device__ __forceinline__ float2 dacc_renorm(const DAcc& A) {
    float hi = __fadd_rn(A.hi, A.err);
    float lo = __fsub_rn(A.err, __fsub_rn(hi, A.hi));
    return make_float2(hi, lo);
}

__device__ __forceinline__ float2 df_add(float2 a, float2 b) {
    float s, e; two_sum(a.x, b.x, s, e);
    e = __fadd_rn(e, __fadd_rn(a.y, b.y));
    float hi = __fadd_rn(s, e);
    float lo = __fsub_rn(e, __fsub_rn(hi, s));
    return make_float2(hi, lo);
}

__device__ __forceinline__ float2 df_sub(float2 a, float2 b) {
    return df_add(a, make_float2(-b.x, -b.y));
}

__device__ __forceinline__ float2 df_scale2(float2 a) {
    return make_float2(__fmul_rn(a.x, 2.f), __fmul_rn(a.y, 2.f));
}

__device__ __forceinline__ float2 df_sqr(float2 a) {
    float p = __fmul_rn(a.x, a.x);
    float e = __fmaf_rn(a.x, a.x, -p);
    e = __fmaf_rn(__fmul_rn(2.f, a.x), a.y, e);
    return make_float2(p, e);
}

__device__ __forceinline__ float2 df_sqrt(float2 a) {
    if (!(a.x > 1e-37f)) {
        float h = a.x > 0.f ? a.x : 0.f;
        return make_float2(__fsqrt_rn(h), 0.f);
    }
    float y = __fsqrt_rn(a.x);
    float p = __fmul_rn(y, y);
    float e = __fmaf_rn(y, y, -p);
    float d = __fsub_rn(a.x, p);
    float num = __fadd_rn(d, __fsub_rn(a.y, e));
    float c = __fdividef(num, __fmul_rn(2.f, y));
    float hi = __fadd_rn(y, c);
    float lo = __fsub_rn(c, __fsub_rn(hi, y));
    return make_float2(hi, lo);
}

// ---------------------------------------------------------------------------
// df64 single-pixel recompute (same operation order as the validated df64 A).
// DIR=false skips the gx/gy accumulators (gate-only calls).
// ---------------------------------------------------------------------------
template <bool DIR>
__device__ void gm_df(const float* __restrict__ img, const float* __restrict__ gv,
                      int q, int y, int x, float& fgm, float& fgx, float& fgy)
{
    DAcc MAG, GXS, GYS;
    dacc_init(MAG); dacc_init(GXS); dacc_init(GYS);

    for (int c = 0; c < 3; ++c) {
        const float* __restrict__ src = img + (size_t)(q * 3 + c) * HW;

        float raw[7][7];
        #pragma unroll
        for (int ry = 0; ry < 7; ++ry) {
            int yy = y - 3 + ry;
            bool rowok = (unsigned)yy < IMG_H;
            #pragma unroll
            for (int rx = 0; rx < 7; ++rx) {
                int xx = x - 3 + rx;
                raw[ry][rx] = (rowok && (unsigned)xx < IMG_W) ? src[yy * IMG_W + xx] : 0.f;
            }
        }

        float2 hb[7][3];
        #pragma unroll
        for (int ry = 0; ry < 7; ++ry) {
            #pragma unroll
            for (int rx = 0; rx < 3; ++rx) {
                DAcc A; dacc_init(A);
                dacc_fmaff(A, gv[0], raw[ry][rx]);
                dacc_fmaff(A, gv[1], raw[ry][rx + 1]);
                dacc_fmaff(A, gv[2], raw[ry][rx + 2]);
                dacc_fmaff(A, gv[3], raw[ry][rx + 3]);
                dacc_fmaff(A, gv[4], raw[ry][rx + 4]);
                hb[ry][rx] = dacc_renorm(A);
            }
        }

        float2 bl[3][3];
        #pragma unroll
        for (int by = 0; by < 3; ++by) {
            int yy = y - 1 + by;
            #pragma unroll
            for (int bx = 0; bx < 3; ++bx) {
                int xx = x - 1 + bx;
                float2 v = make_float2(0.f, 0.f);
                if ((unsigned)yy < IMG_H && (unsigned)xx < IMG_W) {
                    DAcc A; dacc_init(A);
                    dacc_fmadf(A, hb[by][bx],     gv[0]);
                    dacc_fmadf(A, hb[by + 1][bx], gv[1]);
                    dacc_fmadf(A, hb[by + 2][bx], gv[2]);
                    dacc_fmadf(A, hb[by + 3][bx], gv[3]);
                    dacc_fmadf(A, hb[by + 4][bx], gv[4]);
                    v = dacc_renorm(A);
                }
                bl[by][bx] = v;
            }
        }

        float2 gx = df_add(df_add(df_sub(bl[0][0], bl[0][2]), df_sub(bl[2][0], bl[2][2])),
                           df_scale2(df_sub(bl[1][0], bl[1][2])));
        float2 gy = df_add(df_add(df_sub(bl[0][0], bl[2][0]), df_sub(bl[0][2], bl[2][2])),
                           df_scale2(df_sub(bl[0][1], bl[2][1])));

        float2 m = df_sqrt(df_add(df_sqr(gx), df_sqr(gy)));
        dacc_adddf(MAG, m);
        if (DIR) { dacc_adddf(GXS, gx); dacc_adddf(GYS, gy); }
    }
    fgm = dacc_renorm(MAG).x;
    if (DIR) { fgx = dacc_renorm(GXS).x; fgy = dacc_renorm(GYS).x; }
}

// ---------------------------------------------------------------------------
// Kernel A (fp32 fast path): blur+sobel+mag/orient, plus orientation margin.
// (round-7 structure verbatim — linear loops, pixel-major gm writes)
// ---------------------------------------------------------------------------
__global__ __launch_bounds__(256) void canny_grad_fp32(
    const float* __restrict__ img, const float* __restrict__ gw)
{
    if (blockIdx.x == 0 && blockIdx.y == 0 && blockIdx.z == 0 &&
        threadIdx.x == 0 && threadIdx.y == 0)
        g_flag_count = 0;          // reset flag list for this pipeline run

    const int b  = blockIdx.z;
    const int x0 = blockIdx.x * 32;
    const int y0 = blockIdx.y * 32;
    const int tid = threadIdx.y * 32 + threadIdx.x;

    __shared__ float s_raw[38][40];
    __shared__ float s_hb[38][36];
    __shared__ float s_bl[34][36];

    const float g0 = gw[0], g1 = gw[1], g2 = gw[2], g3 = gw[3], g4 = gw[4];

    float mag[4] = {0.f, 0.f, 0.f, 0.f};
    float gxs[4] = {0.f, 0.f, 0.f, 0.f};
    float gys[4] = {0.f, 0.f, 0.f, 0.f};

    for (int c = 0; c < 3; ++c) {
        const float* __restrict__ src = img + (size_t)(b * 3 + c) * HW;

        for (int i = tid; i < 38 * 38; i += 256) {
            int r = i / 38, cc = i % 38;
            int gy = y0 - 3 + r, gx = x0 - 3 + cc;
            float v = 0.f;
            if ((unsigned)gy < IMG_H && (unsigned)gx < IMG_W) v = src[gy * IMG_W + gx];
            s_raw[r][cc] = v;
        }
        __syncthreads();

        for (int i = tid; i < 38 * 34; i += 256) {
            int r = i / 34, cc = i % 34;
            s_hb[r][cc] = g0 * s_raw[r][cc] + g1 * s_raw[r][cc + 1] +
                          g2 * s_raw[r][cc + 2] + g3 * s_raw[r][cc + 3] +
                          g4 * s_raw[r][cc + 4];
        }
        __syncthreads();

        for (int i = tid; i < 34 * 34; i += 256) {
            int r = i / 34, cc = i % 34;
            int gy = y0 - 1 + r, gx = x0 - 1 + cc;
            float v = 0.f;
            if ((unsigned)gy < IMG_H && (unsigned)gx < IMG_W)
                v = g0 * s_hb[r][cc] + g1 * s_hb[r + 1][cc] + g2 * s_hb[r + 2][cc] +
                    g3 * s_hb[r + 3][cc] + g4 * s_hb[r + 4][cc];
            s_bl[r][cc] = v;
        }
        __syncthreads();

        const int tx = threadIdx.x;
        #pragma unroll
        for (int k = 0; k < 4; ++k) {
            int row = threadIdx.y + k * 8;
            float b00 = s_bl[row][tx],     b01 = s_bl[row][tx + 1],     b02 = s_bl[row][tx + 2];
            float b10 = s_bl[row + 1][tx],                              b12 = s_bl[row + 1][tx + 2];
            float b20 = s_bl[row + 2][tx], b21 = s_bl[row + 2][tx + 1], b22 = s_bl[row + 2][tx + 2];
            float gx = (b00 - b02) + 2.f * (b10 - b12) + (b20 - b22);
            float gy = (b00 + 2.f * b01 + b02) - (b20 + 2.f * b21 + b22);
            mag[k] += sqrtf(gx * gx + gy * gy);
            gxs[k] += gx;
            gys[k] += gy;
        }
        __syncthreads();
    }

    const int tx = threadIdx.x;
    #pragma unroll
    for (int k = 0; k < 4; ++k) {
        int row = threadIdx.y + k * 8;
        int y = y0 + row, x = x0 + tx;
        int pix = y * IMG_W + x;

        float t = atan2f(gys[k], gxs[k]);
        float o = t * 57.29577951308232f + 180.0f;
        float u = o / 45.0f;
        float kf = rintf(u);
        int ip = ((int)kf) & 7;

        // orientation margin: distance of u to the bucket boundary (half-int)
        float fl = floorf(u);
        float d  = fabsf((u - fl) - 0.5f);
        float r  = sqrtf(gxs[k] * gxs[k] + gys[k] * gys[k]);
        bool unc = (d * r < EPS_O) || (d < 4e-5f);
        int iplo = ((int)fl) & 7;
        int iphi = ((int)fl + 1) & 7;
        int alt  = (ip == iplo) ? iphi : iplo;

        g_gmt[(size_t)pix * NB + b] = mag[k];
        g_idx[(size_t)b * HW + pix] =
            (unsigned char)(ip | (unc ? 8 : 0) | (alt << 4));
    }
}

// ---------------------------------------------------------------------------
// Kernel B: NMS + threshold + hysteresis (fp32), thin store + uncertainty flags.
// (round-7 structure verbatim)
// ---------------------------------------------------------------------------
__global__ __launch_bounds__(256) void canny_nms_kernel(float* __restrict__ out)
{
    const int x0 = blockIdx.x * 32;
    const int y0 = blockIdx.y * 32;
    const int tid = threadIdx.y * 32 + threadIdx.x;
    const int tx = threadIdx.x;

    __shared__ float s_gm[NB][36][38];
    __shared__ float s_thin[34][36];

    for (int i = tid; i < 36 * 36; i += 256) {
        int r = i / 36, cc = i % 36;
        int y = y0 - 2 + r, x = x0 - 2 + cc;
        if ((unsigned)y < IMG_H && (unsigned)x < IMG_W) {
            const float4* p = reinterpret_cast<const float4*>(&g_gmt[(size_t)(y * IMG_W + x) * NB]);
            float4 v0 = p[0], v1 = p[1];
            s_gm[0][r][cc] = v0.x; s_gm[1][r][cc] = v0.y;
            s_gm[2][r][cc] = v0.z; s_gm[3][r][cc] = v0.w;
            s_gm[4][r][cc] = v1.x; s_gm[5][r][cc] = v1.y;
            s_gm[6][r][cc] = v1.z; s_gm[7][r][cc] = v1.w;
        } else {
            #pragma unroll
            for (int p = 0; p < 8; ++p) s_gm[p][r][cc] = 0.f;
        }
    }
    __syncthreads();

    for (int b = 0; b < NB; ++b) {
        const int dy = c_dy[b], dx = c_dx[b];

        for (int i = tid; i < 34 * 34; i += 256) {
            int r = i / 34, cc = i % 34;
            int y = y0 - 1 + r, x = x0 - 1 + cc;
            float thin = 0.f;
            if ((unsigned)y < IMG_H && (unsigned)x < IMG_W) {
                int pix = y * IMG_W + x;
                int byte = g_idx[(size_t)b * HW + pix];
                int ip  = byte & 7;
                int in_ = (ip + 4) & 7;
                int gr = r + 1, gc = cc + 1;
                float sp = s_gm[ip][gr][gc]  - s_gm[ip][gr + dy][gc + dx];
                float sn = s_gm[in_][gr][gc] - s_gm[in_][gr + dy][gc + dx];
                float mn = fminf(sp, sn);
                bool gate = mn > 0.f;
                float gmb = s_gm[b][gr][gc];
                if (gate) thin = gmb;

                // core pixels: store thin + flag uncertain decisions
                if (r >= 1 && r <= 32 && cc >= 1 && cc <= 32) {
                    g_thin[(size_t)b * HW + pix] = thin;
                    if (gmb > 2.5f - EPS_T) {       // relevance filter
                        bool unc = fabsf(mn) < EPS_G;
                        if (!unc && gate &&
                            (fabsf(gmb - 2.5f) < EPS_T || fabsf(gmb - 5.f) < EPS_T))
                            unc = true;
                        if (!unc && (byte & 8)) {   // orientation near boundary
                            int ia  = (byte >> 4) & 7;
                            int ina = (ia + 4) & 7;
                            float sp2 = s_gm[ia][gr][gc]  - s_gm[ia][gr + dy][gc + dx];
                            float sn2 = s_gm[ina][gr][gc] - s_gm[ina][gr + dy][gc + dx];
                            float mn2 = fminf(sp2, sn2);
                            if ((mn2 > 0.f) != gate || fabsf(mn2) < EPS_G) unc = true;
                        }
                        if (unc) {
                            int s = atomicAdd(&g_flag_count, 1);
                            if (s < MAX_FLAGS)
                                g_flags[s] = ((unsigned)b << 20) | ((unsigned)y << 10) | (unsigned)x;
                        }
                    }
                }
            }
            s_thin[r][cc] = thin;
        }
        __syncthreads();

        #pragma unroll
        for (int k = 0; k < 4; ++k) {
            int ty = threadIdx.y + k * 8;
            int y = y0 + ty, x = x0 + tx;
            float t = s_thin[ty + 1][tx + 1];
            float res;
            if (t > 5.0f) {
                res = 1.f;
            } else if (t >= 2.5f) {
                bool any =
                    s_thin[ty][tx]     > 5.f || s_thin[ty][tx + 1]     > 5.f || s_thin[ty][tx + 2]     > 5.f ||
                    s_thin[ty + 1][tx] > 5.f ||                                 s_thin[ty + 1][tx + 2] > 5.f ||
                    s_thin[ty + 2][tx] > 5.f || s_thin[ty + 2][tx + 1] > 5.f || s_thin[ty + 2][tx + 2] > 5.f;
                res = any ? 1.f : 0.f;
            } else {
                res = 0.f;
            }
            if (y == 0 || y == IMG_H - 1 || x == 0 || x == IMG_W - 1) res = 0.f;
            out[(size_t)b * HW + y * IMG_W + x] = res;
        }
        __syncthreads();
    }
}

// ---------------------------------------------------------------------------
// Kernel C: exact df64 recompute of flagged thin pixels, patch g_thin.
// ---------------------------------------------------------------------------
__global__ __launch_bounds__(256) void canny_fix_kernel(
    const float* __restrict__ img, const float* __restrict__ gw)
{
    int i = blockIdx.x * blockDim.x + threadIdx.x;
    int n = g_flag_count;
    if (n > MAX_FLAGS) n = MAX_FLAGS;
    if (i >= n) return;

    unsigned f = g_flags[i];
    int b = f >> 20, y = (f >> 10) & 1023, x = f & 1023;

    float gv[5];
    #pragma unroll
    for (int k = 0; k < 5; ++k) gv[k] = gw[k];

    float fgm, fgx, fgy;
    gm_df<true>(img, gv, b, y, x, fgm, fgx, fgy);

    float t = atan2f(fgy, fgx);
    float o = __fadd_rn(__fmul_rn(t, 57.29577951308232f), 180.0f);
    float kf = rintf(__fdiv_rn(o, 45.0f));
    int ip  = ((int)kf) & 7;
    int in_ = (ip + 4) & 7;

    int dy = c_dy[b], dx = c_dx[b];
    int y2 = y + dy, x2 = x + dx;
    bool nb_ok = (unsigned)y2 < IMG_H && (unsigned)x2 < IMG_W;

    float dd1, dd2;
    float a0, a1, c0, c1;
    gm_df<false>(img, gv, ip, y, x, a0, dd1, dd2);
    if (nb_ok) gm_df<false>(img, gv, ip, y2, x2, a1, dd1, dd2); else a1 = 0.f;
    gm_df<false>(img, gv, in_, y, x, c0, dd1, dd2);
    if (nb_ok) gm_df<false>(img, gv, in_, y2, x2, c1, dd1, dd2); else c1 = 0.f;

    float sp = __fsub_rn(a0, a1);
    float sn = __fsub_rn(c0, c1);
    float thin = (fminf(sp, sn) > 0.f) ? fgm : 0.f;
    g_thin[(size_t)b * HW + y * IMG_W + x] = thin;
}

// ---------------------------------------------------------------------------
// Kernel D: re-classify 3x3 outputs around each corrected thin pixel.
// ---------------------------------------------------------------------------
__global__ __launch_bounds__(256) void canny_reclass_kernel(float* __restrict__ out)
{
    int i = blockIdx.x * blockDim.x + threadIdx.x;
    int n = g_flag_count;
    if (n > MAX_FLAGS) n = MAX_FLAGS;
    if (i >= n) return;

    unsigned f = g_flags[i];
    int b = f >> 20, y = (f >> 10) & 1023, x = f & 1023;
    const float* tb = &g_thin[(size_t)b * HW];

    #pragma unroll
    for (int dy2 = -1; dy2 <= 1; ++dy2) {
        #pragma unroll
        for (int dx2 = -1; dx2 <= 1; ++dx2) {
            int yo = y + dy2, xo = x + dx2;
            if ((unsigned)yo >= IMG_H || (unsigned)xo >= IMG_W) continue;
            float res = 0.f;
            if (yo > 0 && yo < IMG_H - 1 && xo > 0 && xo < IMG_W - 1) {
                float t = tb[yo * IMG_W + xo];
                if (t > 5.0f) {
                    res = 1.f;
                } else if (t >= 2.5f) {
                    bool any =
                        tb[(yo - 1) * IMG_W + xo - 1] > 5.f || tb[(yo - 1) * IMG_W + xo] > 5.f || tb[(yo - 1) * IMG_W + xo + 1] > 5.f ||
                        tb[yo * IMG_W + xo - 1]       > 5.f ||                                     tb[yo * IMG_W + xo + 1]       > 5.f ||
                        tb[(yo + 1) * IMG_W + xo - 1] > 5.f || tb[(yo + 1) * IMG_W + xo] > 5.f || tb[(yo + 1) * IMG_W + xo + 1] > 5.f;
                    res = any ? 1.f : 0.f;
                }
            }
            out[(size_t)b * HW + yo * IMG_W + xo] = res;
        }
    }
}

// ---------------------------------------------------------------------------
extern "C" void kernel_launch(void* const* d_in, const int* in_sizes, int n_in,
                              void* d_out, int out_size)
{
    const float* img   = (const float*)d_in[0];  // (8,3,1024,1024)
    const float* gauss = (const float*)d_in[1];  // gauss_h (1,1,1,5)
    (void)in_sizes; (void)n_in; (void)out_size;

    dim3 blkA(32, 8);
    dim3 gridA(IMG_W / 32, IMG_H / 32, NB);
    canny_grad_fp32<<<gridA, blkA>>>(img, gauss);

    dim3 blkB(32, 8);
    dim3 gridB(IMG_W / 32, IMG_H / 32);
    canny_nms_kernel<<<gridB, blkB>>>((float*)d_out);

    canny_fix_kernel<<<MAX_FLAGS / 256, 256>>>(img, gauss);
    canny_reclass_kernel<<<MAX_FLAGS / 256, 256>>>((float*)d_out);
}